// round 13
// baseline (speedup 1.0000x reference)
#include <cuda_runtime.h>
#include <math.h>

// Problem constants
#define B_    32
#define C_    256
#define CR_   64
#define HW_   12544       // 112*112 floats per channel
#define NCH   (B_*C_)     // 8192 channels
#define KEEP  2048        // tail channels pinned in L2 (~103 MB) [R7 value]

// v8 (32B) tiling: 12544/8 = 1568 = 6*256 + 32
#define NF8   6
#define NT8   32
// float4 tiling: 3136 = 12*256 + 64
#define NF4   12
#define NT4   64

__device__ float    g_gap[NCH];
__device__ float    g_gate[NCH];
__device__ unsigned g_ticket;   // monotonically increasing; 8192 | 2^32

struct F8 { float4 a, b; };

__device__ __forceinline__ F8 ld_evict_last8(const float* p) {
    unsigned r0,r1,r2,r3,r4,r5,r6,r7;
    asm("ld.global.L2::evict_last.v8.b32 {%0,%1,%2,%3,%4,%5,%6,%7}, [%8];"
        : "=r"(r0),"=r"(r1),"=r"(r2),"=r"(r3),
          "=r"(r4),"=r"(r5),"=r"(r6),"=r"(r7) : "l"(p));
    F8 v;
    v.a.x = __uint_as_float(r0); v.a.y = __uint_as_float(r1);
    v.a.z = __uint_as_float(r2); v.a.w = __uint_as_float(r3);
    v.b.x = __uint_as_float(r4); v.b.y = __uint_as_float(r5);
    v.b.z = __uint_as_float(r6); v.b.w = __uint_as_float(r7);
    return v;
}

__device__ __forceinline__ F8 ld_evict_first8(const float* p) {
    unsigned r0,r1,r2,r3,r4,r5,r6,r7;
    asm("ld.global.L2::evict_first.v8.b32 {%0,%1,%2,%3,%4,%5,%6,%7}, [%8];"
        : "=r"(r0),"=r"(r1),"=r"(r2),"=r"(r3),
          "=r"(r4),"=r"(r5),"=r"(r6),"=r"(r7) : "l"(p));
    F8 v;
    v.a.x = __uint_as_float(r0); v.a.y = __uint_as_float(r1);
    v.a.z = __uint_as_float(r2); v.a.w = __uint_as_float(r3);
    v.b.x = __uint_as_float(r4); v.b.y = __uint_as_float(r5);
    v.b.z = __uint_as_float(r6); v.b.w = __uint_as_float(r7);
    return v;
}

// ---------------------------------------------------------------------------
// Kernel 1: GAP + fused FC. One CTA per channel; 32B loads; tail channels
// pinned in L2. The LAST CTA to finish (atomic ticket) computes all gates.
// ---------------------------------------------------------------------------
__global__ __launch_bounds__(256) void gap_kernel(
    const float* __restrict__ x,
    const float* __restrict__ w1, const float* __restrict__ b1,
    const float* __restrict__ w2, const float* __restrict__ b2) {
    const int bc = blockIdx.x;
    const int t  = threadIdx.x;
    const float* __restrict__ base = x + (size_t)bc * HW_;
    const bool keep = (bc >= NCH - KEEP);

    F8 v[NF8];
    F8 vt;
    if (keep) {
        #pragma unroll
        for (int k = 0; k < NF8; ++k)
            v[k] = ld_evict_last8(base + (t + k * 256) * 8);
        if (t < NT8) vt = ld_evict_last8(base + (t + NF8 * 256) * 8);
    } else {
        #pragma unroll
        for (int k = 0; k < NF8; ++k)
            v[k] = ld_evict_first8(base + (t + k * 256) * 8);
        if (t < NT8) vt = ld_evict_first8(base + (t + NF8 * 256) * 8);
    }

    float sum = 0.0f;
    #pragma unroll
    for (int k = 0; k < NF8; ++k)
        sum += ((v[k].a.x + v[k].a.y) + (v[k].a.z + v[k].a.w))
             + ((v[k].b.x + v[k].b.y) + (v[k].b.z + v[k].b.w));
    if (t < NT8)
        sum += ((vt.a.x + vt.a.y) + (vt.a.z + vt.a.w))
             + ((vt.b.x + vt.b.y) + (vt.b.z + vt.b.w));

    #pragma unroll
    for (int o = 16; o > 0; o >>= 1)
        sum += __shfl_xor_sync(0xFFFFFFFFu, sum, o);

    __shared__ float s[8];
    __shared__ unsigned is_last;
    if ((t & 31) == 0) s[t >> 5] = sum;
    __syncthreads();
    if (t < 8) {
        sum = s[t];
        #pragma unroll
        for (int o = 4; o > 0; o >>= 1)
            sum += __shfl_xor_sync(0xFFu, sum, o);
        if (t == 0)
            g_gap[bc] = sum * (1.0f / (float)HW_);
    }

    // -------- last-CTA election (no reset needed: 8192 divides 2^32) --------
    if (t == 0) {
        __threadfence();                       // publish g_gap[bc]
        unsigned tk = atomicAdd(&g_ticket, 1u);
        is_last = (((tk + 1u) & (NCH - 1u)) == 0u);
    }
    __syncthreads();
    if (!is_last) return;

    // -------- fused FC: this CTA computes all 32*256 gates --------
    __shared__ float gap_s[NCH > 8192 ? 1 : 8192];   // 32 KB
    __shared__ float h_s[B_ * CR_];                  // 8 KB

    const volatile float* gg = (const volatile float*)g_gap;
    #pragma unroll
    for (int i = 0; i < NCH / 256; ++i)
        gap_s[t + i * 256] = gg[t + i * 256];
    __syncthreads();

    // hidden: 2048 units = 32 batches x 64
    #pragma unroll
    for (int i = 0; i < (B_ * CR_) / 256; ++i) {
        const int idx = t + i * 256;
        const int b = idx >> 6, o = idx & 63;
        float acc = b1[o];
        const float* __restrict__ w = w1 + o * C_;
        const float* __restrict__ gp = gap_s + b * C_;
        #pragma unroll 8
        for (int c = 0; c < C_; ++c) acc = fmaf(gp[c], w[c], acc);
        h_s[idx] = fmaxf(acc, 0.0f);
    }
    __syncthreads();

    // gates: 8192 = 32 batches x 256
    #pragma unroll
    for (int i = 0; i < NCH / 256; ++i) {
        const int idx = t + i * 256;
        const int b = idx >> 8, c = idx & 255;
        float acc = b2[c];
        const float* __restrict__ w = w2 + c * CR_;
        const float* __restrict__ hp = h_s + b * CR_;
        #pragma unroll 8
        for (int o = 0; o < CR_; ++o) acc = fmaf(hp[o], w[o], acc);
        g_gate[idx] = 1.0f / (1.0f + __expf(-acc));
    }
    // kernel boundary orders g_gate before scale_kernel reads it
}

// ---------------------------------------------------------------------------
// Kernel 2: out = x * gate[bc]. One CTA per channel, reverse order (pinned
// tail first). __ldlu last-use reads; __stcs streaming stores. [R7 form]
// ---------------------------------------------------------------------------
__global__ __launch_bounds__(256) void scale_kernel(
    const float* __restrict__ x, float* __restrict__ out) {
    const int bc = NCH - 1 - (int)blockIdx.x;   // reverse order
    const int t  = threadIdx.x;
    const float g = g_gate[bc];
    const float4* __restrict__ xp =
        reinterpret_cast<const float4*>(x + (size_t)bc * HW_);
    float4* __restrict__ op =
        reinterpret_cast<float4*>(out + (size_t)bc * HW_);

    float4 v[NF4];
    #pragma unroll
    for (int k = 0; k < NF4; ++k)
        v[k] = __ldlu(xp + t + k * 256);
    float4 vt;
    if (t < NT4) vt = __ldlu(xp + t + NF4 * 256);

    #pragma unroll
    for (int k = 0; k < NF4; ++k) {
        v[k].x *= g; v[k].y *= g; v[k].z *= g; v[k].w *= g;
        __stcs(op + t + k * 256, v[k]);
    }
    if (t < NT4) {
        vt.x *= g; vt.y *= g; vt.z *= g; vt.w *= g;
        __stcs(op + t + NF4 * 256, vt);
    }
}

// ---------------------------------------------------------------------------
extern "C" void kernel_launch(void* const* d_in, const int* in_sizes, int n_in,
                              void* d_out, int out_size) {
    const float* x  = (const float*)d_in[0];
    const float* w1 = (const float*)d_in[1];
    const float* b1 = (const float*)d_in[2];
    const float* w2 = (const float*)d_in[3];
    const float* b2 = (const float*)d_in[4];
    float* out = (float*)d_out;

    gap_kernel<<<NCH, 256>>>(x, w1, b1, w2, b2);
    scale_kernel<<<NCH, 256>>>(x, out);
}

// round 14
// speedup vs baseline: 3.8697x; 3.8697x over previous
#include <cuda_runtime.h>
#include <math.h>

// Problem constants
#define B_    32
#define C_    256
#define CR_   64
#define HW_   12544       // 112*112 floats per channel
#define NCH   (B_*C_)     // 8192 channels
#define KEEP  2048        // tail channels pinned in L2 (~103 MB)

// v8 (32B) tiling: 12544/8 = 1568 = 6*256 + 32
#define NF8   6
#define NT8   32
// float4 tiling: 3136 = 12*256 + 64
#define NF4   12
#define NT4   64

__device__ float    g_gap[NCH];
__device__ float    g_h[B_ * CR_];
__device__ unsigned g_tick[B_];   // +256 per launch each; (tk+1)&255==0 elects one CTA

struct F8 { float4 a, b; };

__device__ __forceinline__ F8 ld_evict_last8(const float* p) {
    unsigned r0,r1,r2,r3,r4,r5,r6,r7;
    asm("ld.global.L2::evict_last.v8.b32 {%0,%1,%2,%3,%4,%5,%6,%7}, [%8];"
        : "=r"(r0),"=r"(r1),"=r"(r2),"=r"(r3),
          "=r"(r4),"=r"(r5),"=r"(r6),"=r"(r7) : "l"(p));
    F8 v;
    v.a.x = __uint_as_float(r0); v.a.y = __uint_as_float(r1);
    v.a.z = __uint_as_float(r2); v.a.w = __uint_as_float(r3);
    v.b.x = __uint_as_float(r4); v.b.y = __uint_as_float(r5);
    v.b.z = __uint_as_float(r6); v.b.w = __uint_as_float(r7);
    return v;
}

__device__ __forceinline__ F8 ld_evict_first8(const float* p) {
    unsigned r0,r1,r2,r3,r4,r5,r6,r7;
    asm("ld.global.L2::evict_first.v8.b32 {%0,%1,%2,%3,%4,%5,%6,%7}, [%8];"
        : "=r"(r0),"=r"(r1),"=r"(r2),"=r"(r3),
          "=r"(r4),"=r"(r5),"=r"(r6),"=r"(r7) : "l"(p));
    F8 v;
    v.a.x = __uint_as_float(r0); v.a.y = __uint_as_float(r1);
    v.a.z = __uint_as_float(r2); v.a.w = __uint_as_float(r3);
    v.b.x = __uint_as_float(r4); v.b.y = __uint_as_float(r5);
    v.b.z = __uint_as_float(r6); v.b.w = __uint_as_float(r7);
    return v;
}

// ---------------------------------------------------------------------------
// Kernel 1: GAP + per-batch hidden layer. One CTA per channel; 32B loads;
// tail channels pinned in L2. Last CTA of each batch (ticket) computes h[b,:].
// Extra smem: ~1 KB -> occupancy unchanged vs R7.
// ---------------------------------------------------------------------------
__global__ __launch_bounds__(256) void gap_kernel(
    const float* __restrict__ x,
    const float* __restrict__ w1, const float* __restrict__ b1) {
    const int bc = blockIdx.x;
    const int b  = bc >> 8;          // batch index (C_ == 256)
    const int t  = threadIdx.x;
    const float* __restrict__ base = x + (size_t)bc * HW_;
    const bool keep = (bc >= NCH - KEEP);

    F8 v[NF8];
    F8 vt;
    if (keep) {
        #pragma unroll
        for (int k = 0; k < NF8; ++k)
            v[k] = ld_evict_last8(base + (t + k * 256) * 8);
        if (t < NT8) vt = ld_evict_last8(base + (t + NF8 * 256) * 8);
    } else {
        #pragma unroll
        for (int k = 0; k < NF8; ++k)
            v[k] = ld_evict_first8(base + (t + k * 256) * 8);
        if (t < NT8) vt = ld_evict_first8(base + (t + NF8 * 256) * 8);
    }

    float sum = 0.0f;
    #pragma unroll
    for (int k = 0; k < NF8; ++k)
        sum += ((v[k].a.x + v[k].a.y) + (v[k].a.z + v[k].a.w))
             + ((v[k].b.x + v[k].b.y) + (v[k].b.z + v[k].b.w));
    if (t < NT8)
        sum += ((vt.a.x + vt.a.y) + (vt.a.z + vt.a.w))
             + ((vt.b.x + vt.b.y) + (vt.b.z + vt.b.w));

    #pragma unroll
    for (int o = 16; o > 0; o >>= 1)
        sum += __shfl_xor_sync(0xFFFFFFFFu, sum, o);

    __shared__ float s[8];
    __shared__ unsigned last_sh;
    if ((t & 31) == 0) s[t >> 5] = sum;
    __syncthreads();
    if (t < 8) {
        sum = s[t];
        #pragma unroll
        for (int o = 4; o > 0; o >>= 1)
            sum += __shfl_xor_sync(0xFFu, sum, o);
        if (t == 0)
            g_gap[bc] = sum * (1.0f / (float)HW_);
    }

    // ---- per-batch last-CTA election (exactly 256 arrivals per launch) ----
    if (t == 0) {
        __threadfence();                              // publish g_gap[bc]
        unsigned tk = atomicAdd(&g_tick[b], 1u);
        last_sh = (((tk + 1u) & 255u) == 0u) ? 1u : 0u;
    }
    __syncthreads();
    if (!last_sh) return;

    // ---- elected CTA: hidden layer h[b, 0:64] ----
    __threadfence();  // acquire: see all g_gap writes of this batch
    __shared__ float gap_s[C_];
    const volatile float* gg = (const volatile float*)g_gap + b * C_;
    gap_s[t] = gg[t];
    __syncthreads();

    if (t < CR_) {
        float acc = b1[t];
        const float* __restrict__ w = w1 + t * C_;
        #pragma unroll 8
        for (int c = 0; c < C_; ++c) acc = fmaf(gap_s[c], w[c], acc);
        g_h[b * CR_ + t] = fmaxf(acc, 0.0f);
    }
    // kernel boundary orders g_h before scale_kernel reads it
}

// ---------------------------------------------------------------------------
// Kernel 2: out = x * gate[bc]. One CTA per channel, reverse order (pinned
// tail first). Warp 0 computes the gate scalar (64 FMA + sigmoid) from g_h,
// then the R7-proven streaming body: __ldlu reads, __stcs stores.
// ---------------------------------------------------------------------------
__global__ __launch_bounds__(256) void scale_kernel(
    const float* __restrict__ x, float* __restrict__ out,
    const float* __restrict__ w2, const float* __restrict__ b2) {
    const int bc = NCH - 1 - (int)blockIdx.x;   // reverse order
    const int b  = bc >> 8;
    const int c  = bc & 255;
    const int t  = threadIdx.x;

    __shared__ float gsh;
    if (t < 32) {
        // lanes 0..31 each take o = t and o = t+32
        const float* __restrict__ hp = g_h + b * CR_;
        const float* __restrict__ w  = w2 + c * CR_;
        float acc = fmaf(hp[t], w[t], fmaf(hp[t + 32], w[t + 32], 0.0f));
        #pragma unroll
        for (int o = 16; o > 0; o >>= 1)
            acc += __shfl_xor_sync(0xFFFFFFFFu, acc, o);
        if (t == 0)
            gsh = 1.0f / (1.0f + __expf(-(acc + b2[c])));
    }
    __syncthreads();
    const float g = gsh;

    const float4* __restrict__ xp =
        reinterpret_cast<const float4*>(x + (size_t)bc * HW_);
    float4* __restrict__ op =
        reinterpret_cast<float4*>(out + (size_t)bc * HW_);

    float4 v[NF4];
    #pragma unroll
    for (int k = 0; k < NF4; ++k)
        v[k] = __ldlu(xp + t + k * 256);
    float4 vt;
    if (t < NT4) vt = __ldlu(xp + t + NF4 * 256);

    #pragma unroll
    for (int k = 0; k < NF4; ++k) {
        v[k].x *= g; v[k].y *= g; v[k].z *= g; v[k].w *= g;
        __stcs(op + t + k * 256, v[k]);
    }
    if (t < NT4) {
        vt.x *= g; vt.y *= g; vt.z *= g; vt.w *= g;
        __stcs(op + t + NF4 * 256, vt);
    }
}

// ---------------------------------------------------------------------------
extern "C" void kernel_launch(void* const* d_in, const int* in_sizes, int n_in,
                              void* d_out, int out_size) {
    const float* x  = (const float*)d_in[0];
    const float* w1 = (const float*)d_in[1];
    const float* b1 = (const float*)d_in[2];
    const float* w2 = (const float*)d_in[3];
    const float* b2 = (const float*)d_in[4];
    float* out = (float*)d_out;

    gap_kernel<<<NCH, 256>>>(x, w1, b1);
    scale_kernel<<<NCH, 256>>>(x, out, w2, b2);
}

// round 15
// speedup vs baseline: 3.8776x; 1.0020x over previous
#include <cuda_runtime.h>
#include <math.h>

// Problem constants
#define B_    32
#define C_    256
#define CR_   64
#define HW_   12544       // 112*112 floats per channel
#define NCH   (B_*C_)     // 8192 channels
#define KEEP  2048        // tail channels pinned in L2 (~103 MB)

// v8 (32B) tiling: 12544/8 = 1568 = 6*256 + 32
#define NF8   6
#define NT8   32
// float4 tiling: 3136 = 12*256 + 64
#define NF4   12
#define NT4   64

__device__ float    g_gap[NCH];
__device__ float    g_h[B_ * CR_];
__device__ unsigned g_tick[B_];   // +256 per launch each; (tk+1)&255==0 elects one CTA

struct F8 { float4 a, b; };

__device__ __forceinline__ F8 ld_evict_last8(const float* p) {
    unsigned r0,r1,r2,r3,r4,r5,r6,r7;
    asm("ld.global.L2::evict_last.v8.b32 {%0,%1,%2,%3,%4,%5,%6,%7}, [%8];"
        : "=r"(r0),"=r"(r1),"=r"(r2),"=r"(r3),
          "=r"(r4),"=r"(r5),"=r"(r6),"=r"(r7) : "l"(p));
    F8 v;
    v.a.x = __uint_as_float(r0); v.a.y = __uint_as_float(r1);
    v.a.z = __uint_as_float(r2); v.a.w = __uint_as_float(r3);
    v.b.x = __uint_as_float(r4); v.b.y = __uint_as_float(r5);
    v.b.z = __uint_as_float(r6); v.b.w = __uint_as_float(r7);
    return v;
}

__device__ __forceinline__ F8 ld_evict_first8(const float* p) {
    unsigned r0,r1,r2,r3,r4,r5,r6,r7;
    asm("ld.global.L2::evict_first.v8.b32 {%0,%1,%2,%3,%4,%5,%6,%7}, [%8];"
        : "=r"(r0),"=r"(r1),"=r"(r2),"=r"(r3),
          "=r"(r4),"=r"(r5),"=r"(r6),"=r"(r7) : "l"(p));
    F8 v;
    v.a.x = __uint_as_float(r0); v.a.y = __uint_as_float(r1);
    v.a.z = __uint_as_float(r2); v.a.w = __uint_as_float(r3);
    v.b.x = __uint_as_float(r4); v.b.y = __uint_as_float(r5);
    v.b.z = __uint_as_float(r6); v.b.w = __uint_as_float(r7);
    return v;
}

// ---------------------------------------------------------------------------
// Kernel 1: GAP + per-batch hidden layer. One CTA per channel; 32B loads;
// tail channels pinned in L2. Last CTA of each batch (ticket) computes h[b,:].
// ---------------------------------------------------------------------------
__global__ __launch_bounds__(256) void gap_kernel(
    const float* __restrict__ x,
    const float* __restrict__ w1, const float* __restrict__ b1) {
    const int bc = blockIdx.x;
    const int b  = bc >> 8;          // batch index (C_ == 256)
    const int t  = threadIdx.x;
    const float* __restrict__ base = x + (size_t)bc * HW_;
    const bool keep = (bc >= NCH - KEEP);

    F8 v[NF8];
    F8 vt;
    if (keep) {
        #pragma unroll
        for (int k = 0; k < NF8; ++k)
            v[k] = ld_evict_last8(base + (t + k * 256) * 8);
        if (t < NT8) vt = ld_evict_last8(base + (t + NF8 * 256) * 8);
    } else {
        #pragma unroll
        for (int k = 0; k < NF8; ++k)
            v[k] = ld_evict_first8(base + (t + k * 256) * 8);
        if (t < NT8) vt = ld_evict_first8(base + (t + NF8 * 256) * 8);
    }

    float sum = 0.0f;
    #pragma unroll
    for (int k = 0; k < NF8; ++k)
        sum += ((v[k].a.x + v[k].a.y) + (v[k].a.z + v[k].a.w))
             + ((v[k].b.x + v[k].b.y) + (v[k].b.z + v[k].b.w));
    if (t < NT8)
        sum += ((vt.a.x + vt.a.y) + (vt.a.z + vt.a.w))
             + ((vt.b.x + vt.b.y) + (vt.b.z + vt.b.w));

    #pragma unroll
    for (int o = 16; o > 0; o >>= 1)
        sum += __shfl_xor_sync(0xFFFFFFFFu, sum, o);

    __shared__ float s[8];
    __shared__ unsigned last_sh;
    if ((t & 31) == 0) s[t >> 5] = sum;
    __syncthreads();
    if (t < 8) {
        sum = s[t];
        #pragma unroll
        for (int o = 4; o > 0; o >>= 1)
            sum += __shfl_xor_sync(0xFFu, sum, o);
        if (t == 0)
            g_gap[bc] = sum * (1.0f / (float)HW_);
    }

    // ---- per-batch last-CTA election (exactly 256 arrivals per launch) ----
    if (t == 0) {
        __threadfence();                              // publish g_gap[bc]
        unsigned tk = atomicAdd(&g_tick[b], 1u);
        last_sh = (((tk + 1u) & 255u) == 0u) ? 1u : 0u;
    }
    __syncthreads();
    if (!last_sh) return;

    // ---- elected CTA: hidden layer h[b, 0:64] ----
    __threadfence();  // acquire: see all g_gap writes of this batch
    __shared__ float gap_s[C_];
    const volatile float* gg = (const volatile float*)g_gap + b * C_;
    gap_s[t] = gg[t];
    __syncthreads();

    if (t < CR_) {
        float acc = b1[t];
        const float* __restrict__ w = w1 + t * C_;
        #pragma unroll 8
        for (int c = 0; c < C_; ++c) acc = fmaf(gap_s[c], w[c], acc);
        g_h[b * CR_ + t] = fmaxf(acc, 0.0f);
    }
    // kernel boundary orders g_h before scale_kernel reads it
}

// ---------------------------------------------------------------------------
// Kernel 2: out = x * gate[bc]. One CTA per channel, reverse order (pinned
// tail first). STREAMING LOADS ISSUED FIRST (independent of gate), then the
// gate dot-product latency is hidden under them; finally multiply + store.
// ---------------------------------------------------------------------------
__global__ __launch_bounds__(256) void scale_kernel(
    const float* __restrict__ x, float* __restrict__ out,
    const float* __restrict__ w2, const float* __restrict__ b2) {
    const int bc = NCH - 1 - (int)blockIdx.x;   // reverse order
    const int b  = bc >> 8;
    const int c  = bc & 255;
    const int t  = threadIdx.x;

    const float4* __restrict__ xp =
        reinterpret_cast<const float4*>(x + (size_t)bc * HW_);
    float4* __restrict__ op =
        reinterpret_cast<float4*>(out + (size_t)bc * HW_);

    // ---- 1. issue all streaming loads (no dependence on the gate) ----
    float4 v[NF4];
    #pragma unroll
    for (int k = 0; k < NF4; ++k)
        v[k] = __ldlu(xp + t + k * 256);
    float4 vt;
    if (t < NT4) vt = __ldlu(xp + t + NF4 * 256);

    // ---- 2. gate dot-product (warp 0), overlapped with loads in flight ----
    __shared__ float gsh;
    if (t < 32) {
        const float* __restrict__ hp = g_h + b * CR_;
        const float* __restrict__ w  = w2 + c * CR_;
        float acc = fmaf(hp[t], w[t], fmaf(hp[t + 32], w[t + 32], 0.0f));
        #pragma unroll
        for (int o = 16; o > 0; o >>= 1)
            acc += __shfl_xor_sync(0xFFFFFFFFu, acc, o);
        if (t == 0)
            gsh = 1.0f / (1.0f + __expf(-(acc + b2[c])));
    }
    __syncthreads();
    const float g = gsh;

    // ---- 3. scale + streaming stores ----
    #pragma unroll
    for (int k = 0; k < NF4; ++k) {
        v[k].x *= g; v[k].y *= g; v[k].z *= g; v[k].w *= g;
        __stcs(op + t + k * 256, v[k]);
    }
    if (t < NT4) {
        vt.x *= g; vt.y *= g; vt.z *= g; vt.w *= g;
        __stcs(op + t + NF4 * 256, vt);
    }
}

// ---------------------------------------------------------------------------
extern "C" void kernel_launch(void* const* d_in, const int* in_sizes, int n_in,
                              void* d_out, int out_size) {
    const float* x  = (const float*)d_in[0];
    const float* w1 = (const float*)d_in[1];
    const float* b1 = (const float*)d_in[2];
    const float* w2 = (const float*)d_in[3];
    const float* b2 = (const float*)d_in[4];
    float* out = (float*)d_out;

    gap_kernel<<<NCH, 256>>>(x, w1, b1);
    scale_kernel<<<NCH, 256>>>(x, out, w2, b2);
}